// round 7
// baseline (speedup 1.0000x reference)
#include <cuda_runtime.h>
#include <cuda_bf16.h>
#include <cstdint>

// Problem constants
#define T_DIM   64
#define NCH     2048
#define KDIM    65536
#define THRESHV 16384.0f
#define KWTA    16

// GEMM config: 16 n-blocks x SPLITK 9 = 144 CTAs (~1 per SM, balanced wave)
#define SPLITK  9
#define BK      16
#define CHTOT   (KDIM / BK)       // 4096 chunks; split 0 gets 456, others 455

// fp32 staging ring: 4 stages x (A 64x16 fp32 = 4KB, B 128x16 fp32 = 8KB)
#define FPSTG   12288
#define FP_B    4096
// bf16 ring: 3 stages x 18432 (AH 0, AL 3072, BH 6144, BL 12288; 48B row stride)
#define BFBASE  49152
#define BFSTG   18432
#define RSTRIDE 48
#define AH_OFF  0
#define AL_OFF  3072
#define BH_OFF  6144
#define BL_OFF  12288
#define SMEM_TOTAL (BFBASE + 3 * BFSTG)   // 104448

// Static scratch (no allocations allowed)
__device__ float g_partial[SPLITK][T_DIM * NCH];
__device__ float g_pot[T_DIM * NCH];
__device__ int   g_cnt[NCH];
__device__ float g_fp[NCH];
__device__ float g_coef[NCH];

// ---------------------------------------------------------------------------
// Helpers
// ---------------------------------------------------------------------------
__device__ __forceinline__ uint32_t smem_u32(const void* p) {
    uint32_t a;
    asm("{ .reg .u64 t; cvta.to.shared.u64 t, %1; cvt.u32.u64 %0, t; }"
        : "=r"(a) : "l"(p));
    return a;
}
__device__ __forceinline__ void cp16(uint32_t dst, const void* src) {
    asm volatile("cp.async.cg.shared.global [%0], [%1], 16;"
                 :: "r"(dst), "l"(src) : "memory");
}
#define CP_COMMIT() asm volatile("cp.async.commit_group;" ::: "memory")
#define CP_WAIT(n)  asm volatile("cp.async.wait_group %0;" :: "n"(n) : "memory")

// Split float2 -> hi bf16x2 (RN) + lo bf16x2 (residual). Proven exact R3-R6.
__device__ __forceinline__ void split2(float x, float y, uint32_t& h, uint32_t& l) {
    asm("cvt.rn.bf16x2.f32 %0, %1, %2;" : "=r"(h) : "f"(y), "f"(x));
    float hx = __uint_as_float(h << 16);
    float hy = __uint_as_float(h & 0xFFFF0000u);
    float lx = x - hx;
    float ly = y - hy;
    asm("cvt.rn.bf16x2.f32 %0, %1, %2;" : "=r"(l) : "f"(ly), "f"(lx));
}

__device__ __forceinline__ void mma16816(float* c, const uint32_t* a,
                                         uint32_t b0, uint32_t b1) {
    asm volatile(
        "mma.sync.aligned.m16n8k16.row.col.f32.bf16.bf16.f32 "
        "{%0,%1,%2,%3}, {%4,%5,%6,%7}, {%8,%9}, {%0,%1,%2,%3};"
        : "+f"(c[0]), "+f"(c[1]), "+f"(c[2]), "+f"(c[3])
        : "r"(a[0]), "r"(a[1]), "r"(a[2]), "r"(a[3]), "r"(b0), "r"(b1));
}

__device__ __forceinline__ void ldsm4(uint32_t* r, uint32_t addr) {
    asm volatile("ldmatrix.sync.aligned.m8n8.x4.shared.b16 {%0,%1,%2,%3}, [%4];"
                 : "=r"(r[0]), "=r"(r[1]), "=r"(r[2]), "=r"(r[3]) : "r"(addr));
}

__device__ __forceinline__ void cvt_sts(const char* fp, char* hiP, char* loP) {
    float4 v = *(const float4*)fp;
    uint32_t h0, l0, h1, l1;
    split2(v.x, v.y, h0, l0);
    split2(v.z, v.w, h1, l1);
    *(uint2*)hiP = make_uint2(h0, h1);
    *(uint2*)loP = make_uint2(l0, l1);
}

// ---------------------------------------------------------------------------
// Kernel 1: bf16 HMMA split-K GEMM (structure proven in R6; balanced grid).
// ---------------------------------------------------------------------------
__global__ void __launch_bounds__(256, 1)
gemm_mma(const float* __restrict__ rec, const float* __restrict__ w) {
    extern __shared__ char sm[];
    const uint32_t sbase = smem_u32(sm);

    const int tid  = threadIdx.x;
    const int wid  = tid >> 5;
    const int lane = tid & 31;
    const int g    = lane >> 2;
    const int q    = lane & 3;
    const int wm   = wid >> 2;
    const int wn   = wid & 3;
    const int nblk = blockIdx.x * 128;
    const int s    = blockIdx.y;
    const int nit  = s ? 455 : 456;                       // chunks this split
    const size_t k0 = (size_t)(s ? s * 455 + 1 : 0) * BK; // start K element

    const int lr  = tid >> 2;
    const int lkc = (tid & 3) * 4;
    const float* aS  = rec + (size_t)lr * KDIM + k0 + lkc;
    const float* bS0 = w + (size_t)(nblk + lr) * KDIM + k0 + lkc;
    const float* bS1 = bS0 + (size_t)64 * KDIM;
    const uint32_t fpA = (uint32_t)lr * 64 + lkc * 4;
    const uint32_t fpB = FP_B + (uint32_t)lr * 64 + lkc * 4;
    const uint32_t bfO = (uint32_t)lr * RSTRIDE + lkc * 2;

    const int j  = lane >> 3;
    const int l7 = lane & 7;
    const uint32_t aOff = (uint32_t)(wm * 32 + (j & 1) * 8 + l7) * RSTRIDE
                        + (j >> 1) * 16 + AH_OFF;
    const uint32_t bOff = (uint32_t)(wn * 32 + (j >> 1) * 8 + l7) * RSTRIDE
                        + (j & 1) * 16 + BH_OFF;

    float acc[2][4][4];
    #pragma unroll
    for (int m = 0; m < 2; m++)
        #pragma unroll
        for (int n = 0; n < 4; n++)
            #pragma unroll
            for (int i = 0; i < 4; i++) acc[m][n][i] = 0.0f;

    // Prologue: stage chunks 0..2; convert chunk 0 -> bf stage 0
    #pragma unroll
    for (int st = 0; st < 3; st++) {
        const uint32_t fo = sbase + st * FPSTG;
        const int co = st * BK;
        cp16(fo + fpA, aS + co);
        cp16(fo + fpB, bS0 + co);
        cp16(fo + fpB + 4096, bS1 + co);
        CP_COMMIT();
    }
    CP_WAIT(2);
    {
        const char* fs = sm;
        char* bs = sm + BFBASE;
        cvt_sts(fs + fpA, bs + AH_OFF + bfO, bs + AL_OFF + bfO);
        cvt_sts(fs + fpB, bs + BH_OFF + bfO, bs + BL_OFF + bfO);
        cvt_sts(fs + fpB + 4096, bs + BH_OFF + 3072 + bfO, bs + BL_OFF + 3072 + bfO);
    }

    int bfc = 0;

    #pragma unroll 1
    for (int it = 0; it < nit; it++) {
        const int nc = it + 3;
        if (nc < nit) {
            const uint32_t fo = sbase + (nc & 3) * FPSTG;
            const int co = nc * BK;
            cp16(fo + fpA, aS + co);
            cp16(fo + fpB, bS0 + co);
            cp16(fo + fpB + 4096, bS1 + co);
        }
        CP_COMMIT();
        CP_WAIT(2);
        __syncthreads();

        const int bfn = (bfc == 2) ? 0 : bfc + 1;
        if (it + 1 < nit) {
            const char* fs = sm + ((it + 1) & 3) * FPSTG;
            char* bs = sm + BFBASE + bfn * BFSTG;
            cvt_sts(fs + fpA, bs + AH_OFF + bfO, bs + AL_OFF + bfO);
            cvt_sts(fs + fpB, bs + BH_OFF + bfO, bs + BL_OFF + bfO);
            cvt_sts(fs + fpB + 4096, bs + BH_OFF + 3072 + bfO,
                    bs + BL_OFF + 3072 + bfO);
        }

        const uint32_t sb = sbase + BFBASE + bfc * BFSTG;
        uint32_t Ah0[4], Ah1[4], Al0[4], Al1[4];
        ldsm4(Ah0, sb + aOff);
        ldsm4(Ah1, sb + aOff + 16 * RSTRIDE);
        ldsm4(Al0, sb + aOff + (AL_OFF - AH_OFF));
        ldsm4(Al1, sb + aOff + (AL_OFF - AH_OFF) + 16 * RSTRIDE);
        uint32_t Bh0[4], Bh1[4], Bl0[4], Bl1[4];
        ldsm4(Bh0, sb + bOff);
        ldsm4(Bh1, sb + bOff + 16 * RSTRIDE);
        ldsm4(Bl0, sb + bOff + (BL_OFF - BH_OFF));
        ldsm4(Bl1, sb + bOff + (BL_OFF - BH_OFF) + 16 * RSTRIDE);

        const uint32_t* Bh[4] = { &Bh0[0], &Bh0[2], &Bh1[0], &Bh1[2] };
        const uint32_t* Bl[4] = { &Bl0[0], &Bl0[2], &Bl1[0], &Bl1[2] };
        const uint32_t* Ah[2] = { Ah0, Ah1 };
        const uint32_t* Al[2] = { Al0, Al1 };

        #pragma unroll
        for (int m = 0; m < 2; m++) {
            #pragma unroll
            for (int n = 0; n < 4; n++) {
                mma16816(acc[m][n], Ah[m], Bh[n][0], Bh[n][1]);
                mma16816(acc[m][n], Ah[m], Bl[n][0], Bl[n][1]);
                mma16816(acc[m][n], Al[m], Bh[n][0], Bh[n][1]);
            }
        }
        bfc = bfn;
    }

    float* gp = g_partial[s];
    const int t0 = wm * 32;
    #pragma unroll
    for (int m = 0; m < 2; m++) {
        const int r0 = t0 + m * 16 + g;
        #pragma unroll
        for (int n = 0; n < 4; n++) {
            const int cb = nblk + wn * 32 + n * 8 + 2 * q;
            *(float2*)&gp[r0 * NCH + cb]       = make_float2(acc[m][n][0], acc[m][n][1]);
            *(float2*)&gp[(r0 + 8) * NCH + cb] = make_float2(acc[m][n][2], acc[m][n][3]);
        }
    }
}

// ---------------------------------------------------------------------------
// Kernel 2: fused reduce + per-column stats.
// 32 blocks x 256 threads; block b owns columns [b*64, b*64+64) for all t.
// Writes g_pot, g_cnt[k], g_fp[k] (first-spike potential per reference calc).
// ---------------------------------------------------------------------------
__global__ void __launch_bounds__(256)
reduce_stats_kernel() {
    __shared__ int cnt_s[4][64];

    const int tid = threadIdx.x;
    const int c   = tid & 63;
    const int tg  = tid >> 6;            // 0..3 -> t range [tg*16, tg*16+16)
    const int col = blockIdx.x * 64 + c;

    int cnt = 0;
    for (int t = tg * 16; t < tg * 16 + 16; t++) {
        const int idx = t * NCH + col;
        float sum = 0.0f;
        #pragma unroll
        for (int p = 0; p < SPLITK; p++) sum += g_partial[p][idx];
        g_pot[idx] = sum;
        if (sum > THRESHV) cnt++;
    }
    cnt_s[tg][c] = cnt;
    __syncthreads();

    if (tid < 64) {
        int total = cnt_s[0][c] + cnt_s[1][c] + cnt_s[2][c] + cnt_s[3][c];
        int fi = T_DIM - total;
        if (fi > T_DIM - 1) fi = T_DIM - 1;
        if (fi < 0) fi = 0;
        float o  = g_pot[fi * NCH + col];    // own block wrote all t of col
        g_cnt[col] = total;
        g_fp[col]  = (o > THRESHV) ? o : 0.0f;
    }
}

// ---------------------------------------------------------------------------
// Kernel 3: winner selection on 2048 precomputed (cnt, fp) scalars.
//   v = max_k (cnt>0 ? fp : 0) * T ; tot[k] = fold of cnt copies of (fp+v)
//   top-16 (tie -> lowest index), coef = (top_val > 0)
// ---------------------------------------------------------------------------
__global__ void __launch_bounds__(1024)
winners_kernel() {
    __shared__ float tot_s[NCH];
    __shared__ float rv[1024];
    __shared__ int   ri[1024];

    const int tid = threadIdx.x;

    // v = max over k of per-column trunc max
    float m = 0.0f;
    int   cnts[2];
    float fps[2];
    #pragma unroll
    for (int h = 0; h < 2; h++) {
        const int k = tid + h * 1024;
        cnts[h] = g_cnt[k];
        fps[h]  = g_fp[k];
        m = fmaxf(m, (cnts[h] > 0) ? fps[h] : 0.0f);
    }
    rv[tid] = m;
    __syncthreads();
    for (int st = 512; st > 0; st >>= 1) {
        if (tid < st) rv[tid] = fmaxf(rv[tid], rv[tid + st]);
        __syncthreads();
    }
    const float v = rv[0] * (float)T_DIM;
    __syncthreads();

    // tot[k] = sequential fold of cnt copies of (fp + v)
    #pragma unroll
    for (int h = 0; h < 2; h++) {
        const int k = tid + h * 1024;
        const float term = fps[h] + v;
        float sacc = 0.0f;
        for (int i = 0; i < cnts[h]; i++) sacc += term;
        tot_s[k] = sacc;
        g_coef[k] = 0.0f;
    }
    __syncthreads();

    // Iterative top-16 argmax, tie -> lowest index
    for (int it = 0; it < KWTA; it++) {
        float bv = -3.4e38f;
        int   bi = NCH;
        #pragma unroll
        for (int h = 0; h < 2; h++) {
            const int k = tid + h * 1024;
            const float vv = tot_s[k];
            if (vv > bv || (vv == bv && k < bi)) { bv = vv; bi = k; }
        }
        rv[tid] = bv; ri[tid] = bi;
        __syncthreads();
        for (int st = 512; st > 0; st >>= 1) {
            if (tid < st) {
                if (rv[tid + st] > rv[tid] ||
                    (rv[tid + st] == rv[tid] && ri[tid + st] < ri[tid])) {
                    rv[tid] = rv[tid + st];
                    ri[tid] = ri[tid + st];
                }
            }
            __syncthreads();
        }
        if (tid == 0) {
            const int wk = ri[0];
            if (rv[0] > 0.0f) g_coef[wk] = 1.0f;
            tot_s[wk] = -3.4e38f;
        }
        __syncthreads();
    }
}

// ---------------------------------------------------------------------------
// Kernel 4: final spikes
// ---------------------------------------------------------------------------
__global__ void output_kernel(float* __restrict__ out) {
    int i = blockIdx.x * blockDim.x + threadIdx.x;
    if (i < T_DIM * NCH) {
        float o = g_pot[i];
        out[i] = (o > THRESHV && g_coef[i & (NCH - 1)] > 0.0f) ? 1.0f : 0.0f;
    }
}

// ---------------------------------------------------------------------------
extern "C" void kernel_launch(void* const* d_in, const int* in_sizes, int n_in,
                              void* d_out, int out_size) {
    const float* rec = (const float*)d_in[0];   // (64, 1, 256, 256)
    const float* w   = (const float*)d_in[1];   // (2048, 1, 256, 256)
    float* out = (float*)d_out;                 // (64, 2048, 1, 1) float32

    cudaFuncSetAttribute(gemm_mma, cudaFuncAttributeMaxDynamicSharedMemorySize,
                         SMEM_TOTAL);
    dim3 grid(NCH / 128, SPLITK);               // (16, 9) = 144 CTAs, 1/SM
    gemm_mma<<<grid, 256, SMEM_TOTAL>>>(rec, w);
    reduce_stats_kernel<<<NCH / 64, 256>>>();
    winners_kernel<<<1, 1024>>>();
    output_kernel<<<(T_DIM * NCH + 255) / 256, 256>>>(out);
}

// round 8
// speedup vs baseline: 1.3579x; 1.3579x over previous
#include <cuda_runtime.h>
#include <cuda_bf16.h>
#include <cstdint>

// Problem constants
#define T_DIM   64
#define NCH     2048
#define KDIM    65536
#define THRESHV 16384.0f
#define KWTA    16

// GEMM config: 16 n-blocks x SPLITK 18 = 288 CTAs (<= 2 per SM, balanced)
#define SPLITK  18
#define BK      16
#define CHTOT   (KDIM / BK)       // 4096 chunks; splits 0-9: 228, 10-17: 227

// fp32 staging ring: 4 stages x (A 64x16 fp32 = 4KB, B 128x16 fp32 = 8KB)
#define FPSTG   12288
#define FP_B    4096
// bf16 ring: 3 stages x 18432 (AH 0, AL 3072, BH 6144, BL 12288; 48B row stride)
#define BFBASE  49152
#define BFSTG   18432
#define RSTRIDE 48
#define AH_OFF  0
#define AL_OFF  3072
#define BH_OFF  6144
#define BL_OFF  12288
#define SMEM_TOTAL (BFBASE + 3 * BFSTG)   // 104448

// Static scratch (no allocations allowed)
__device__ float g_partial[SPLITK][T_DIM * NCH];   // 9.4 MB
__device__ float g_pot[T_DIM * NCH];
__device__ int   g_cnt[NCH];
__device__ float g_fp[NCH];
__device__ float g_coef[NCH];

// ---------------------------------------------------------------------------
// Helpers
// ---------------------------------------------------------------------------
__device__ __forceinline__ uint32_t smem_u32(const void* p) {
    uint32_t a;
    asm("{ .reg .u64 t; cvta.to.shared.u64 t, %1; cvt.u32.u64 %0, t; }"
        : "=r"(a) : "l"(p));
    return a;
}
__device__ __forceinline__ void cp16(uint32_t dst, const void* src) {
    asm volatile("cp.async.cg.shared.global [%0], [%1], 16;"
                 :: "r"(dst), "l"(src) : "memory");
}
#define CP_COMMIT() asm volatile("cp.async.commit_group;" ::: "memory")
#define CP_WAIT(n)  asm volatile("cp.async.wait_group %0;" :: "n"(n) : "memory")

// Split float2 -> hi bf16x2 (RN) + lo bf16x2 (residual). Proven exact R3-R7.
__device__ __forceinline__ void split2(float x, float y, uint32_t& h, uint32_t& l) {
    asm("cvt.rn.bf16x2.f32 %0, %1, %2;" : "=r"(h) : "f"(y), "f"(x));
    float hx = __uint_as_float(h << 16);
    float hy = __uint_as_float(h & 0xFFFF0000u);
    float lx = x - hx;
    float ly = y - hy;
    asm("cvt.rn.bf16x2.f32 %0, %1, %2;" : "=r"(l) : "f"(ly), "f"(lx));
}

__device__ __forceinline__ void mma16816(float* c, const uint32_t* a,
                                         uint32_t b0, uint32_t b1) {
    asm volatile(
        "mma.sync.aligned.m16n8k16.row.col.f32.bf16.bf16.f32 "
        "{%0,%1,%2,%3}, {%4,%5,%6,%7}, {%8,%9}, {%0,%1,%2,%3};"
        : "+f"(c[0]), "+f"(c[1]), "+f"(c[2]), "+f"(c[3])
        : "r"(a[0]), "r"(a[1]), "r"(a[2]), "r"(a[3]), "r"(b0), "r"(b1));
}

__device__ __forceinline__ void ldsm4(uint32_t* r, uint32_t addr) {
    asm volatile("ldmatrix.sync.aligned.m8n8.x4.shared.b16 {%0,%1,%2,%3}, [%4];"
                 : "=r"(r[0]), "=r"(r[1]), "=r"(r[2]), "=r"(r[3]) : "r"(addr));
}

__device__ __forceinline__ void cvt_sts(const char* fp, char* hiP, char* loP) {
    float4 v = *(const float4*)fp;
    uint32_t h0, l0, h1, l1;
    split2(v.x, v.y, h0, l0);
    split2(v.z, v.w, h1, l1);
    *(uint2*)hiP = make_uint2(h0, h1);
    *(uint2*)loP = make_uint2(l0, l1);
}

// ---------------------------------------------------------------------------
// Kernel 1: bf16 HMMA split-K GEMM (R6 structure, occupancy 2, balanced grid).
//   g_partial[ks][t*NCH + ch] = sum_k rec[t][k] * w[ch][k]
// ---------------------------------------------------------------------------
__global__ void __launch_bounds__(256, 2)
gemm_mma(const float* __restrict__ rec, const float* __restrict__ w) {
    extern __shared__ char sm[];
    const uint32_t sbase = smem_u32(sm);

    const int tid  = threadIdx.x;
    const int wid  = tid >> 5;
    const int lane = tid & 31;
    const int g    = lane >> 2;
    const int q    = lane & 3;
    const int wm   = wid >> 2;
    const int wn   = wid & 3;
    const int nblk = blockIdx.x * 128;
    const int s    = blockIdx.y;
    // Chunk split: splits 0..9 get 228, splits 10..17 get 227
    const int nit  = (s < 10) ? 228 : 227;
    const int ch0  = (s < 10) ? s * 228 : 2280 + (s - 10) * 227;
    const size_t k0 = (size_t)ch0 * BK;

    const int lr  = tid >> 2;
    const int lkc = (tid & 3) * 4;
    const float* aS  = rec + (size_t)lr * KDIM + k0 + lkc;
    const float* bS0 = w + (size_t)(nblk + lr) * KDIM + k0 + lkc;
    const float* bS1 = bS0 + (size_t)64 * KDIM;
    const uint32_t fpA = (uint32_t)lr * 64 + lkc * 4;
    const uint32_t fpB = FP_B + (uint32_t)lr * 64 + lkc * 4;
    const uint32_t bfO = (uint32_t)lr * RSTRIDE + lkc * 2;

    const int j  = lane >> 3;
    const int l7 = lane & 7;
    const uint32_t aOff = (uint32_t)(wm * 32 + (j & 1) * 8 + l7) * RSTRIDE
                        + (j >> 1) * 16 + AH_OFF;
    const uint32_t bOff = (uint32_t)(wn * 32 + (j >> 1) * 8 + l7) * RSTRIDE
                        + (j & 1) * 16 + BH_OFF;

    float acc[2][4][4];
    #pragma unroll
    for (int m = 0; m < 2; m++)
        #pragma unroll
        for (int n = 0; n < 4; n++)
            #pragma unroll
            for (int i = 0; i < 4; i++) acc[m][n][i] = 0.0f;

    // Prologue: stage chunks 0..2; convert chunk 0 -> bf stage 0
    #pragma unroll
    for (int st = 0; st < 3; st++) {
        const uint32_t fo = sbase + st * FPSTG;
        const int co = st * BK;
        cp16(fo + fpA, aS + co);
        cp16(fo + fpB, bS0 + co);
        cp16(fo + fpB + 4096, bS1 + co);
        CP_COMMIT();
    }
    CP_WAIT(2);
    {
        const char* fs = sm;
        char* bs = sm + BFBASE;
        cvt_sts(fs + fpA, bs + AH_OFF + bfO, bs + AL_OFF + bfO);
        cvt_sts(fs + fpB, bs + BH_OFF + bfO, bs + BL_OFF + bfO);
        cvt_sts(fs + fpB + 4096, bs + BH_OFF + 3072 + bfO, bs + BL_OFF + 3072 + bfO);
    }

    int bfc = 0;

    #pragma unroll 1
    for (int it = 0; it < nit; it++) {
        const int nc = it + 3;
        if (nc < nit) {
            const uint32_t fo = sbase + (nc & 3) * FPSTG;
            const int co = nc * BK;
            cp16(fo + fpA, aS + co);
            cp16(fo + fpB, bS0 + co);
            cp16(fo + fpB + 4096, bS1 + co);
        }
        CP_COMMIT();
        CP_WAIT(2);
        __syncthreads();

        const int bfn = (bfc == 2) ? 0 : bfc + 1;
        if (it + 1 < nit) {
            const char* fs = sm + ((it + 1) & 3) * FPSTG;
            char* bs = sm + BFBASE + bfn * BFSTG;
            cvt_sts(fs + fpA, bs + AH_OFF + bfO, bs + AL_OFF + bfO);
            cvt_sts(fs + fpB, bs + BH_OFF + bfO, bs + BL_OFF + bfO);
            cvt_sts(fs + fpB + 4096, bs + BH_OFF + 3072 + bfO,
                    bs + BL_OFF + 3072 + bfO);
        }

        const uint32_t sb = sbase + BFBASE + bfc * BFSTG;
        uint32_t Ah0[4], Ah1[4], Al0[4], Al1[4];
        ldsm4(Ah0, sb + aOff);
        ldsm4(Ah1, sb + aOff + 16 * RSTRIDE);
        ldsm4(Al0, sb + aOff + (AL_OFF - AH_OFF));
        ldsm4(Al1, sb + aOff + (AL_OFF - AH_OFF) + 16 * RSTRIDE);
        uint32_t Bh0[4], Bh1[4], Bl0[4], Bl1[4];
        ldsm4(Bh0, sb + bOff);
        ldsm4(Bh1, sb + bOff + 16 * RSTRIDE);
        ldsm4(Bl0, sb + bOff + (BL_OFF - BH_OFF));
        ldsm4(Bl1, sb + bOff + (BL_OFF - BH_OFF) + 16 * RSTRIDE);

        const uint32_t* Bh[4] = { &Bh0[0], &Bh0[2], &Bh1[0], &Bh1[2] };
        const uint32_t* Bl[4] = { &Bl0[0], &Bl0[2], &Bl1[0], &Bl1[2] };
        const uint32_t* Ah[2] = { Ah0, Ah1 };
        const uint32_t* Al[2] = { Al0, Al1 };

        #pragma unroll
        for (int m = 0; m < 2; m++) {
            #pragma unroll
            for (int n = 0; n < 4; n++) {
                mma16816(acc[m][n], Ah[m], Bh[n][0], Bh[n][1]);
                mma16816(acc[m][n], Ah[m], Bl[n][0], Bl[n][1]);
                mma16816(acc[m][n], Al[m], Bh[n][0], Bh[n][1]);
            }
        }
        bfc = bfn;
    }

    float* gp = g_partial[s];
    const int t0 = wm * 32;
    #pragma unroll
    for (int m = 0; m < 2; m++) {
        const int r0 = t0 + m * 16 + g;
        #pragma unroll
        for (int n = 0; n < 4; n++) {
            const int cb = nblk + wn * 32 + n * 8 + 2 * q;
            *(float2*)&gp[r0 * NCH + cb]       = make_float2(acc[m][n][0], acc[m][n][1]);
            *(float2*)&gp[(r0 + 8) * NCH + cb] = make_float2(acc[m][n][2], acc[m][n][3]);
        }
    }
}

// ---------------------------------------------------------------------------
// Kernel 2: fused reduce + per-column stats.
// 32 blocks x 256 threads; block b owns columns [b*64, b*64+64) for all t.
// ---------------------------------------------------------------------------
__global__ void __launch_bounds__(256)
reduce_stats_kernel() {
    __shared__ int cnt_s[4][64];

    const int tid = threadIdx.x;
    const int c   = tid & 63;
    const int tg  = tid >> 6;            // 0..3 -> t range [tg*16, tg*16+16)
    const int col = blockIdx.x * 64 + c;

    int cnt = 0;
    for (int t = tg * 16; t < tg * 16 + 16; t++) {
        const int idx = t * NCH + col;
        float sum = 0.0f;
        #pragma unroll
        for (int p = 0; p < SPLITK; p++) sum += g_partial[p][idx];
        g_pot[idx] = sum;
        if (sum > THRESHV) cnt++;
    }
    cnt_s[tg][c] = cnt;
    __syncthreads();

    if (tid < 64) {
        int total = cnt_s[0][c] + cnt_s[1][c] + cnt_s[2][c] + cnt_s[3][c];
        int fi = T_DIM - total;
        if (fi > T_DIM - 1) fi = T_DIM - 1;
        if (fi < 0) fi = 0;
        float o  = g_pot[fi * NCH + col];
        g_cnt[col] = total;
        g_fp[col]  = (o > THRESHV) ? o : 0.0f;
    }
}

// ---------------------------------------------------------------------------
// Kernel 3: winner selection on 2048 precomputed (cnt, fp) scalars.
// ---------------------------------------------------------------------------
__global__ void __launch_bounds__(1024)
winners_kernel() {
    __shared__ float tot_s[NCH];
    __shared__ float rv[1024];
    __shared__ int   ri[1024];

    const int tid = threadIdx.x;

    float m = 0.0f;
    int   cnts[2];
    float fps[2];
    #pragma unroll
    for (int h = 0; h < 2; h++) {
        const int k = tid + h * 1024;
        cnts[h] = g_cnt[k];
        fps[h]  = g_fp[k];
        m = fmaxf(m, (cnts[h] > 0) ? fps[h] : 0.0f);
    }
    rv[tid] = m;
    __syncthreads();
    for (int st = 512; st > 0; st >>= 1) {
        if (tid < st) rv[tid] = fmaxf(rv[tid], rv[tid + st]);
        __syncthreads();
    }
    const float v = rv[0] * (float)T_DIM;
    __syncthreads();

    #pragma unroll
    for (int h = 0; h < 2; h++) {
        const int k = tid + h * 1024;
        const float term = fps[h] + v;
        float sacc = 0.0f;
        for (int i = 0; i < cnts[h]; i++) sacc += term;
        tot_s[k] = sacc;
        g_coef[k] = 0.0f;
    }
    __syncthreads();

    for (int it = 0; it < KWTA; it++) {
        float bv = -3.4e38f;
        int   bi = NCH;
        #pragma unroll
        for (int h = 0; h < 2; h++) {
            const int k = tid + h * 1024;
            const float vv = tot_s[k];
            if (vv > bv || (vv == bv && k < bi)) { bv = vv; bi = k; }
        }
        rv[tid] = bv; ri[tid] = bi;
        __syncthreads();
        for (int st = 512; st > 0; st >>= 1) {
            if (tid < st) {
                if (rv[tid + st] > rv[tid] ||
                    (rv[tid + st] == rv[tid] && ri[tid + st] < ri[tid])) {
                    rv[tid] = rv[tid + st];
                    ri[tid] = ri[tid + st];
                }
            }
            __syncthreads();
        }
        if (tid == 0) {
            const int wk = ri[0];
            if (rv[0] > 0.0f) g_coef[wk] = 1.0f;
            tot_s[wk] = -3.4e38f;
        }
        __syncthreads();
    }
}

// ---------------------------------------------------------------------------
// Kernel 4: final spikes
// ---------------------------------------------------------------------------
__global__ void output_kernel(float* __restrict__ out) {
    int i = blockIdx.x * blockDim.x + threadIdx.x;
    if (i < T_DIM * NCH) {
        float o = g_pot[i];
        out[i] = (o > THRESHV && g_coef[i & (NCH - 1)] > 0.0f) ? 1.0f : 0.0f;
    }
}

// ---------------------------------------------------------------------------
extern "C" void kernel_launch(void* const* d_in, const int* in_sizes, int n_in,
                              void* d_out, int out_size) {
    const float* rec = (const float*)d_in[0];   // (64, 1, 256, 256)
    const float* w   = (const float*)d_in[1];   // (2048, 1, 256, 256)
    float* out = (float*)d_out;                 // (64, 2048, 1, 1) float32

    cudaFuncSetAttribute(gemm_mma, cudaFuncAttributeMaxDynamicSharedMemorySize,
                         SMEM_TOTAL);
    dim3 grid(NCH / 128, SPLITK);               // (16, 18) = 288 CTAs, <=2/SM
    gemm_mma<<<grid, 256, SMEM_TOTAL>>>(rec, w);
    reduce_stats_kernel<<<NCH / 64, 256>>>();
    winners_kernel<<<1, 1024>>>();
    output_kernel<<<(T_DIM * NCH + 255) / 256, 256>>>(out);
}

// round 9
// speedup vs baseline: 1.4322x; 1.0547x over previous
#include <cuda_runtime.h>
#include <cuda_bf16.h>
#include <cstdint>

// Problem constants
#define T_DIM   64
#define NCH     2048
#define KDIM    65536
#define THRESHV 16384.0f
#define KWTA    16

// GEMM config: 16 n-blocks x SPLITK 18 = 288 CTAs (<= 2 per SM, balanced)
#define SPLITK  18
#define BK      16

// fp32 staging ring: 4 stages x (A 64x16 fp32 = 4KB, B 128x16 fp32 = 8KB)
#define FPSTG   12288
#define FP_B    4096
// bf16 ring: 3 stages x 18432 (AH 0, AL 3072, BH 6144, BL 12288; 48B row stride)
#define BFBASE  49152
#define BFSTG   18432
#define RSTRIDE 48
#define AH_OFF  0
#define AL_OFF  3072
#define BH_OFF  6144
#define BL_OFF  12288
#define SMEM_TOTAL (BFBASE + 3 * BFSTG)   // 104448

// Static scratch (no allocations allowed)
__device__ float g_partial[SPLITK][T_DIM * NCH];   // 9.4 MB
__device__ int   g_cnt[NCH];
__device__ float g_fp[NCH];
__device__ unsigned int g_tickets = 0;   // monotonic grid-sync counter

// ---------------------------------------------------------------------------
// Helpers
// ---------------------------------------------------------------------------
__device__ __forceinline__ uint32_t smem_u32(const void* p) {
    uint32_t a;
    asm("{ .reg .u64 t; cvta.to.shared.u64 t, %1; cvt.u32.u64 %0, t; }"
        : "=r"(a) : "l"(p));
    return a;
}
__device__ __forceinline__ void cp16(uint32_t dst, const void* src) {
    asm volatile("cp.async.cg.shared.global [%0], [%1], 16;"
                 :: "r"(dst), "l"(src) : "memory");
}
#define CP_COMMIT() asm volatile("cp.async.commit_group;" ::: "memory")
#define CP_WAIT(n)  asm volatile("cp.async.wait_group %0;" :: "n"(n) : "memory")

// Split float2 -> hi bf16x2 (RN) + lo bf16x2 (residual). Proven exact R3-R8.
__device__ __forceinline__ void split2(float x, float y, uint32_t& h, uint32_t& l) {
    asm("cvt.rn.bf16x2.f32 %0, %1, %2;" : "=r"(h) : "f"(y), "f"(x));
    float hx = __uint_as_float(h << 16);
    float hy = __uint_as_float(h & 0xFFFF0000u);
    float lx = x - hx;
    float ly = y - hy;
    asm("cvt.rn.bf16x2.f32 %0, %1, %2;" : "=r"(l) : "f"(ly), "f"(lx));
}

__device__ __forceinline__ void mma16816(float* c, const uint32_t* a,
                                         uint32_t b0, uint32_t b1) {
    asm volatile(
        "mma.sync.aligned.m16n8k16.row.col.f32.bf16.bf16.f32 "
        "{%0,%1,%2,%3}, {%4,%5,%6,%7}, {%8,%9}, {%0,%1,%2,%3};"
        : "+f"(c[0]), "+f"(c[1]), "+f"(c[2]), "+f"(c[3])
        : "r"(a[0]), "r"(a[1]), "r"(a[2]), "r"(a[3]), "r"(b0), "r"(b1));
}

__device__ __forceinline__ void ldsm4(uint32_t* r, uint32_t addr) {
    asm volatile("ldmatrix.sync.aligned.m8n8.x4.shared.b16 {%0,%1,%2,%3}, [%4];"
                 : "=r"(r[0]), "=r"(r[1]), "=r"(r[2]), "=r"(r[3]) : "r"(addr));
}

__device__ __forceinline__ void cvt_sts(const char* fp, char* hiP, char* loP) {
    float4 v = *(const float4*)fp;
    uint32_t h0, l0, h1, l1;
    split2(v.x, v.y, h0, l0);
    split2(v.z, v.w, h1, l1);
    *(uint2*)hiP = make_uint2(h0, h1);
    *(uint2*)loP = make_uint2(l0, l1);
}

// ---------------------------------------------------------------------------
// Kernel 1: bf16 HMMA split-K GEMM (byte-identical structure to R8).
// ---------------------------------------------------------------------------
__global__ void __launch_bounds__(256, 2)
gemm_mma(const float* __restrict__ rec, const float* __restrict__ w) {
    extern __shared__ char sm[];
    const uint32_t sbase = smem_u32(sm);

    const int tid  = threadIdx.x;
    const int wid  = tid >> 5;
    const int lane = tid & 31;
    const int g    = lane >> 2;
    const int q    = lane & 3;
    const int wm   = wid >> 2;
    const int wn   = wid & 3;
    const int nblk = blockIdx.x * 128;
    const int s    = blockIdx.y;
    const int nit  = (s < 10) ? 228 : 227;
    const int ch0  = (s < 10) ? s * 228 : 2280 + (s - 10) * 227;
    const size_t k0 = (size_t)ch0 * BK;

    const int lr  = tid >> 2;
    const int lkc = (tid & 3) * 4;
    const float* aS  = rec + (size_t)lr * KDIM + k0 + lkc;
    const float* bS0 = w + (size_t)(nblk + lr) * KDIM + k0 + lkc;
    const float* bS1 = bS0 + (size_t)64 * KDIM;
    const uint32_t fpA = (uint32_t)lr * 64 + lkc * 4;
    const uint32_t fpB = FP_B + (uint32_t)lr * 64 + lkc * 4;
    const uint32_t bfO = (uint32_t)lr * RSTRIDE + lkc * 2;

    const int j  = lane >> 3;
    const int l7 = lane & 7;
    const uint32_t aOff = (uint32_t)(wm * 32 + (j & 1) * 8 + l7) * RSTRIDE
                        + (j >> 1) * 16 + AH_OFF;
    const uint32_t bOff = (uint32_t)(wn * 32 + (j >> 1) * 8 + l7) * RSTRIDE
                        + (j & 1) * 16 + BH_OFF;

    float acc[2][4][4];
    #pragma unroll
    for (int m = 0; m < 2; m++)
        #pragma unroll
        for (int n = 0; n < 4; n++)
            #pragma unroll
            for (int i = 0; i < 4; i++) acc[m][n][i] = 0.0f;

    #pragma unroll
    for (int st = 0; st < 3; st++) {
        const uint32_t fo = sbase + st * FPSTG;
        const int co = st * BK;
        cp16(fo + fpA, aS + co);
        cp16(fo + fpB, bS0 + co);
        cp16(fo + fpB + 4096, bS1 + co);
        CP_COMMIT();
    }
    CP_WAIT(2);
    {
        const char* fs = sm;
        char* bs = sm + BFBASE;
        cvt_sts(fs + fpA, bs + AH_OFF + bfO, bs + AL_OFF + bfO);
        cvt_sts(fs + fpB, bs + BH_OFF + bfO, bs + BL_OFF + bfO);
        cvt_sts(fs + fpB + 4096, bs + BH_OFF + 3072 + bfO, bs + BL_OFF + 3072 + bfO);
    }

    int bfc = 0;

    #pragma unroll 1
    for (int it = 0; it < nit; it++) {
        const int nc = it + 3;
        if (nc < nit) {
            const uint32_t fo = sbase + (nc & 3) * FPSTG;
            const int co = nc * BK;
            cp16(fo + fpA, aS + co);
            cp16(fo + fpB, bS0 + co);
            cp16(fo + fpB + 4096, bS1 + co);
        }
        CP_COMMIT();
        CP_WAIT(2);
        __syncthreads();

        const int bfn = (bfc == 2) ? 0 : bfc + 1;
        if (it + 1 < nit) {
            const char* fs = sm + ((it + 1) & 3) * FPSTG;
            char* bs = sm + BFBASE + bfn * BFSTG;
            cvt_sts(fs + fpA, bs + AH_OFF + bfO, bs + AL_OFF + bfO);
            cvt_sts(fs + fpB, bs + BH_OFF + bfO, bs + BL_OFF + bfO);
            cvt_sts(fs + fpB + 4096, bs + BH_OFF + 3072 + bfO,
                    bs + BL_OFF + 3072 + bfO);
        }

        const uint32_t sb = sbase + BFBASE + bfc * BFSTG;
        uint32_t Ah0[4], Ah1[4], Al0[4], Al1[4];
        ldsm4(Ah0, sb + aOff);
        ldsm4(Ah1, sb + aOff + 16 * RSTRIDE);
        ldsm4(Al0, sb + aOff + (AL_OFF - AH_OFF));
        ldsm4(Al1, sb + aOff + (AL_OFF - AH_OFF) + 16 * RSTRIDE);
        uint32_t Bh0[4], Bh1[4], Bl0[4], Bl1[4];
        ldsm4(Bh0, sb + bOff);
        ldsm4(Bh1, sb + bOff + 16 * RSTRIDE);
        ldsm4(Bl0, sb + bOff + (BL_OFF - BH_OFF));
        ldsm4(Bl1, sb + bOff + (BL_OFF - BH_OFF) + 16 * RSTRIDE);

        const uint32_t* Bh[4] = { &Bh0[0], &Bh0[2], &Bh1[0], &Bh1[2] };
        const uint32_t* Bl[4] = { &Bl0[0], &Bl0[2], &Bl1[0], &Bl1[2] };
        const uint32_t* Ah[2] = { Ah0, Ah1 };
        const uint32_t* Al[2] = { Al0, Al1 };

        #pragma unroll
        for (int m = 0; m < 2; m++) {
            #pragma unroll
            for (int n = 0; n < 4; n++) {
                mma16816(acc[m][n], Ah[m], Bh[n][0], Bh[n][1]);
                mma16816(acc[m][n], Ah[m], Bl[n][0], Bl[n][1]);
                mma16816(acc[m][n], Al[m], Bh[n][0], Bh[n][1]);
            }
        }
        bfc = bfn;
    }

    float* gp = g_partial[s];
    const int t0 = wm * 32;
    #pragma unroll
    for (int m = 0; m < 2; m++) {
        const int r0 = t0 + m * 16 + g;
        #pragma unroll
        for (int n = 0; n < 4; n++) {
            const int cb = nblk + wn * 32 + n * 8 + 2 * q;
            *(float2*)&gp[r0 * NCH + cb]       = make_float2(acc[m][n][0], acc[m][n][1]);
            *(float2*)&gp[(r0 + 8) * NCH + cb] = make_float2(acc[m][n][2], acc[m][n][3]);
        }
    }
}

// ---------------------------------------------------------------------------
// Kernel 2: fused post-processing. 32 blocks x 256 threads, one grid sync.
// Phase 1: reduce partials -> smem pot tile (block b owns cols [b*64,b*64+64)),
//          per-column cnt / first-pot -> gmem.
// Grid sync (monotonic ticket barrier; replay-safe, all 32 blocks resident).
// Phase 2: every block redundantly computes top-16 winners from 2048 scalars.
// Phase 3: write output slice from smem pot tile.
// ---------------------------------------------------------------------------
__global__ void __launch_bounds__(256)
fused_post(float* __restrict__ out) {
    __shared__ float pot_s[T_DIM][64];      // [t][c] 16 KB
    __shared__ int   cnt_s[4][64];
    __shared__ float tot_s[NCH];            // 8 KB
    __shared__ float coef_s[NCH];           // 8 KB
    __shared__ float rv[256];
    __shared__ int   ri[256];
    __shared__ unsigned int tgt_s;

    const int tid = threadIdx.x;
    const int c   = tid & 63;
    const int tg  = tid >> 6;               // 0..3 -> t range [tg*16, tg*16+16)
    const int col = blockIdx.x * 64 + c;

    // ---- Phase 1: reduce + stats ----
    int cnt = 0;
    for (int t = tg * 16; t < tg * 16 + 16; t++) {
        const int idx = t * NCH + col;
        float sum = 0.0f;
        #pragma unroll
        for (int p = 0; p < SPLITK; p++) sum += g_partial[p][idx];
        pot_s[t][c] = sum;
        if (sum > THRESHV) cnt++;
    }
    cnt_s[tg][c] = cnt;
    __syncthreads();

    if (tid < 64) {
        int total = cnt_s[0][c] + cnt_s[1][c] + cnt_s[2][c] + cnt_s[3][c];
        int fi = T_DIM - total;
        if (fi > T_DIM - 1) fi = T_DIM - 1;
        if (fi < 0) fi = 0;
        float o = pot_s[fi][c];
        g_cnt[col] = total;
        g_fp[col]  = (o > THRESHV) ? o : 0.0f;
    }

    // ---- Grid sync (ticket barrier, monotonic across graph replays) ----
    __threadfence();
    __syncthreads();
    if (tid == 0) {
        unsigned int ticket = atomicAdd(&g_tickets, 1u);
        tgt_s = (ticket / 32u + 1u) * 32u;
    }
    __syncthreads();
    if (tid == 0) {
        volatile unsigned int* vc = &g_tickets;
        while (*vc < tgt_s) { }
    }
    __syncthreads();
    __threadfence();

    // ---- Phase 2: winners (redundant per block; comparator proven R1-R8) ----
    int   cnts[8];
    float fps[8];
    float m = 0.0f;
    #pragma unroll
    for (int h = 0; h < 8; h++) {
        const int k = tid + h * 256;
        cnts[h] = g_cnt[k];
        fps[h]  = g_fp[k];
        m = fmaxf(m, (cnts[h] > 0) ? fps[h] : 0.0f);
    }
    rv[tid] = m;
    __syncthreads();
    for (int st = 128; st > 0; st >>= 1) {
        if (tid < st) rv[tid] = fmaxf(rv[tid], rv[tid + st]);
        __syncthreads();
    }
    const float v = rv[0] * (float)T_DIM;
    __syncthreads();

    #pragma unroll
    for (int h = 0; h < 8; h++) {
        const int k = tid + h * 256;
        const float term = fps[h] + v;
        float sacc = 0.0f;
        for (int i = 0; i < cnts[h]; i++) sacc += term;
        tot_s[k] = sacc;
        coef_s[k] = 0.0f;
    }
    __syncthreads();

    for (int it = 0; it < KWTA; it++) {
        float bv = -3.4e38f;
        int   bi = NCH;
        #pragma unroll
        for (int h = 0; h < 8; h++) {
            const int k = tid + h * 256;
            const float vv = tot_s[k];
            if (vv > bv || (vv == bv && k < bi)) { bv = vv; bi = k; }
        }
        rv[tid] = bv; ri[tid] = bi;
        __syncthreads();
        for (int st = 128; st > 0; st >>= 1) {
            if (tid < st) {
                if (rv[tid + st] > rv[tid] ||
                    (rv[tid + st] == rv[tid] && ri[tid + st] < ri[tid])) {
                    rv[tid] = rv[tid + st];
                    ri[tid] = ri[tid + st];
                }
            }
            __syncthreads();
        }
        if (tid == 0) {
            const int wk = ri[0];
            if (rv[0] > 0.0f) coef_s[wk] = 1.0f;
            tot_s[wk] = -3.4e38f;
        }
        __syncthreads();
    }

    // ---- Phase 3: output from smem pot tile ----
    const float cf = coef_s[col];
    for (int t = tg * 16; t < tg * 16 + 16; t++) {
        out[t * NCH + col] =
            (pot_s[t][c] > THRESHV && cf > 0.0f) ? 1.0f : 0.0f;
    }
}

// ---------------------------------------------------------------------------
extern "C" void kernel_launch(void* const* d_in, const int* in_sizes, int n_in,
                              void* d_out, int out_size) {
    const float* rec = (const float*)d_in[0];   // (64, 1, 256, 256)
    const float* w   = (const float*)d_in[1];   // (2048, 1, 256, 256)
    float* out = (float*)d_out;                 // (64, 2048, 1, 1) float32

    cudaFuncSetAttribute(gemm_mma, cudaFuncAttributeMaxDynamicSharedMemorySize,
                         SMEM_TOTAL);
    dim3 grid(NCH / 128, SPLITK);               // (16, 18) = 288 CTAs, <=2/SM
    gemm_mma<<<grid, 256, SMEM_TOTAL>>>(rec, w);
    fused_post<<<32, 256>>>(out);
}

// round 10
// speedup vs baseline: 1.5641x; 1.0921x over previous
#include <cuda_runtime.h>
#include <cuda_bf16.h>
#include <cstdint>

// Problem constants
#define T_DIM   64
#define NCH     2048
#define KDIM    65536
#define THRESHV 16384.0f
#define KWTA    16

// GEMM config: 16 n-blocks x SPLITK 18 = 288 CTAs (<= 2 per SM, balanced)
#define SPLITK  18
#define BK      16

// fp32 staging ring: 4 stages x (A 64x16 fp32 = 4KB, B 128x16 fp32 = 8KB)
#define FPSTG   12288
#define FP_B    4096
// bf16 ring: 3 stages x 18432 (AH 0, AL 3072, BH 6144, BL 12288; 48B row stride)
#define BFBASE  49152
#define BFSTG   18432
#define RSTRIDE 48
#define AH_OFF  0
#define AL_OFF  3072
#define BH_OFF  6144
#define BL_OFF  12288
#define SMEM_TOTAL (BFBASE + 3 * BFSTG)   // 104448

// Static scratch (no allocations allowed)
__device__ float g_partial[SPLITK][T_DIM * NCH];   // 9.4 MB
__device__ int   g_cnt[NCH];
__device__ float g_fp[NCH];
__device__ unsigned int g_tickets = 0;   // monotonic grid-sync counter

// ---------------------------------------------------------------------------
// Helpers
// ---------------------------------------------------------------------------
__device__ __forceinline__ uint32_t smem_u32(const void* p) {
    uint32_t a;
    asm("{ .reg .u64 t; cvta.to.shared.u64 t, %1; cvt.u32.u64 %0, t; }"
        : "=r"(a) : "l"(p));
    return a;
}
__device__ __forceinline__ void cp16(uint32_t dst, const void* src) {
    asm volatile("cp.async.cg.shared.global [%0], [%1], 16;"
                 :: "r"(dst), "l"(src) : "memory");
}
#define CP_COMMIT() asm volatile("cp.async.commit_group;" ::: "memory")
#define CP_WAIT(n)  asm volatile("cp.async.wait_group %0;" :: "n"(n) : "memory")

// Split float2 -> hi bf16x2 (RN) + lo bf16x2 (residual). Proven exact R3-R9.
__device__ __forceinline__ void split2(float x, float y, uint32_t& h, uint32_t& l) {
    asm("cvt.rn.bf16x2.f32 %0, %1, %2;" : "=r"(h) : "f"(y), "f"(x));
    float hx = __uint_as_float(h << 16);
    float hy = __uint_as_float(h & 0xFFFF0000u);
    float lx = x - hx;
    float ly = y - hy;
    asm("cvt.rn.bf16x2.f32 %0, %1, %2;" : "=r"(l) : "f"(ly), "f"(lx));
}

__device__ __forceinline__ void mma16816(float* c, const uint32_t* a,
                                         uint32_t b0, uint32_t b1) {
    asm volatile(
        "mma.sync.aligned.m16n8k16.row.col.f32.bf16.bf16.f32 "
        "{%0,%1,%2,%3}, {%4,%5,%6,%7}, {%8,%9}, {%0,%1,%2,%3};"
        : "+f"(c[0]), "+f"(c[1]), "+f"(c[2]), "+f"(c[3])
        : "r"(a[0]), "r"(a[1]), "r"(a[2]), "r"(a[3]), "r"(b0), "r"(b1));
}

__device__ __forceinline__ void ldsm4(uint32_t* r, uint32_t addr) {
    asm volatile("ldmatrix.sync.aligned.m8n8.x4.shared.b16 {%0,%1,%2,%3}, [%4];"
                 : "=r"(r[0]), "=r"(r[1]), "=r"(r[2]), "=r"(r[3]) : "r"(addr));
}

__device__ __forceinline__ void cvt_sts(const char* fp, char* hiP, char* loP) {
    float4 v = *(const float4*)fp;
    uint32_t h0, l0, h1, l1;
    split2(v.x, v.y, h0, l0);
    split2(v.z, v.w, h1, l1);
    *(uint2*)hiP = make_uint2(h0, h1);
    *(uint2*)loP = make_uint2(l0, l1);
}

// (val, idx) comparator: higher val wins, tie -> lower idx. Matches lax.top_k.
__device__ __forceinline__ void cmb(float& bv, int& bi, float ov, int oi) {
    if (ov > bv || (ov == bv && oi < bi)) { bv = ov; bi = oi; }
}

// ---------------------------------------------------------------------------
// Kernel 1: bf16 HMMA split-K GEMM (byte-identical structure to R8/R9).
// ---------------------------------------------------------------------------
__global__ void __launch_bounds__(256, 2)
gemm_mma(const float* __restrict__ rec, const float* __restrict__ w) {
    extern __shared__ char sm[];
    const uint32_t sbase = smem_u32(sm);

    const int tid  = threadIdx.x;
    const int wid  = tid >> 5;
    const int lane = tid & 31;
    const int g    = lane >> 2;
    const int q    = lane & 3;
    const int wm   = wid >> 2;
    const int wn   = wid & 3;
    const int nblk = blockIdx.x * 128;
    const int s    = blockIdx.y;
    const int nit  = (s < 10) ? 228 : 227;
    const int ch0  = (s < 10) ? s * 228 : 2280 + (s - 10) * 227;
    const size_t k0 = (size_t)ch0 * BK;

    const int lr  = tid >> 2;
    const int lkc = (tid & 3) * 4;
    const float* aS  = rec + (size_t)lr * KDIM + k0 + lkc;
    const float* bS0 = w + (size_t)(nblk + lr) * KDIM + k0 + lkc;
    const float* bS1 = bS0 + (size_t)64 * KDIM;
    const uint32_t fpA = (uint32_t)lr * 64 + lkc * 4;
    const uint32_t fpB = FP_B + (uint32_t)lr * 64 + lkc * 4;
    const uint32_t bfO = (uint32_t)lr * RSTRIDE + lkc * 2;

    const int j  = lane >> 3;
    const int l7 = lane & 7;
    const uint32_t aOff = (uint32_t)(wm * 32 + (j & 1) * 8 + l7) * RSTRIDE
                        + (j >> 1) * 16 + AH_OFF;
    const uint32_t bOff = (uint32_t)(wn * 32 + (j >> 1) * 8 + l7) * RSTRIDE
                        + (j & 1) * 16 + BH_OFF;

    float acc[2][4][4];
    #pragma unroll
    for (int m = 0; m < 2; m++)
        #pragma unroll
        for (int n = 0; n < 4; n++)
            #pragma unroll
            for (int i = 0; i < 4; i++) acc[m][n][i] = 0.0f;

    #pragma unroll
    for (int st = 0; st < 3; st++) {
        const uint32_t fo = sbase + st * FPSTG;
        const int co = st * BK;
        cp16(fo + fpA, aS + co);
        cp16(fo + fpB, bS0 + co);
        cp16(fo + fpB + 4096, bS1 + co);
        CP_COMMIT();
    }
    CP_WAIT(2);
    {
        const char* fs = sm;
        char* bs = sm + BFBASE;
        cvt_sts(fs + fpA, bs + AH_OFF + bfO, bs + AL_OFF + bfO);
        cvt_sts(fs + fpB, bs + BH_OFF + bfO, bs + BL_OFF + bfO);
        cvt_sts(fs + fpB + 4096, bs + BH_OFF + 3072 + bfO, bs + BL_OFF + 3072 + bfO);
    }

    int bfc = 0;

    #pragma unroll 1
    for (int it = 0; it < nit; it++) {
        const int nc = it + 3;
        if (nc < nit) {
            const uint32_t fo = sbase + (nc & 3) * FPSTG;
            const int co = nc * BK;
            cp16(fo + fpA, aS + co);
            cp16(fo + fpB, bS0 + co);
            cp16(fo + fpB + 4096, bS1 + co);
        }
        CP_COMMIT();
        CP_WAIT(2);
        __syncthreads();

        const int bfn = (bfc == 2) ? 0 : bfc + 1;
        if (it + 1 < nit) {
            const char* fs = sm + ((it + 1) & 3) * FPSTG;
            char* bs = sm + BFBASE + bfn * BFSTG;
            cvt_sts(fs + fpA, bs + AH_OFF + bfO, bs + AL_OFF + bfO);
            cvt_sts(fs + fpB, bs + BH_OFF + bfO, bs + BL_OFF + bfO);
            cvt_sts(fs + fpB + 4096, bs + BH_OFF + 3072 + bfO,
                    bs + BL_OFF + 3072 + bfO);
        }

        const uint32_t sb = sbase + BFBASE + bfc * BFSTG;
        uint32_t Ah0[4], Ah1[4], Al0[4], Al1[4];
        ldsm4(Ah0, sb + aOff);
        ldsm4(Ah1, sb + aOff + 16 * RSTRIDE);
        ldsm4(Al0, sb + aOff + (AL_OFF - AH_OFF));
        ldsm4(Al1, sb + aOff + (AL_OFF - AH_OFF) + 16 * RSTRIDE);
        uint32_t Bh0[4], Bh1[4], Bl0[4], Bl1[4];
        ldsm4(Bh0, sb + bOff);
        ldsm4(Bh1, sb + bOff + 16 * RSTRIDE);
        ldsm4(Bl0, sb + bOff + (BL_OFF - BH_OFF));
        ldsm4(Bl1, sb + bOff + (BL_OFF - BH_OFF) + 16 * RSTRIDE);

        const uint32_t* Bh[4] = { &Bh0[0], &Bh0[2], &Bh1[0], &Bh1[2] };
        const uint32_t* Bl[4] = { &Bl0[0], &Bl0[2], &Bl1[0], &Bl1[2] };
        const uint32_t* Ah[2] = { Ah0, Ah1 };
        const uint32_t* Al[2] = { Al0, Al1 };

        #pragma unroll
        for (int m = 0; m < 2; m++) {
            #pragma unroll
            for (int n = 0; n < 4; n++) {
                mma16816(acc[m][n], Ah[m], Bh[n][0], Bh[n][1]);
                mma16816(acc[m][n], Ah[m], Bl[n][0], Bl[n][1]);
                mma16816(acc[m][n], Al[m], Bh[n][0], Bh[n][1]);
            }
        }
        bfc = bfn;
    }

    float* gp = g_partial[s];
    const int t0 = wm * 32;
    #pragma unroll
    for (int m = 0; m < 2; m++) {
        const int r0 = t0 + m * 16 + g;
        #pragma unroll
        for (int n = 0; n < 4; n++) {
            const int cb = nblk + wn * 32 + n * 8 + 2 * q;
            *(float2*)&gp[r0 * NCH + cb]       = make_float2(acc[m][n][0], acc[m][n][1]);
            *(float2*)&gp[(r0 + 8) * NCH + cb] = make_float2(acc[m][n][2], acc[m][n][3]);
        }
    }
}

// ---------------------------------------------------------------------------
// Kernel 2: fused post-processing. 32 blocks x 1024 threads, one grid sync.
// ---------------------------------------------------------------------------
__global__ void __launch_bounds__(1024)
fused_post(float* __restrict__ out) {
    __shared__ float pot_s[T_DIM][64];      // [t][c] 16 KB
    __shared__ int   cnt_s[16][64];         // 4 KB
    __shared__ float tot_s[NCH];            // 8 KB
    __shared__ float coef_s[NCH];           // 8 KB
    __shared__ float wv[32];
    __shared__ int   wi[32];
    __shared__ float bc_v;                  // broadcast slots
    __shared__ unsigned int tgt_s;

    const int tid  = threadIdx.x;
    const int lane = tid & 31;
    const int wid  = tid >> 5;
    const int c    = tid & 63;
    const int tg   = tid >> 6;              // 0..15 -> t range [tg*4, tg*4+4)
    const int col  = blockIdx.x * 64 + c;

    // ---- Phase 1: reduce partials -> pot tile + per-column stats ----
    int cnt = 0;
    #pragma unroll
    for (int tt = 0; tt < 4; tt++) {
        const int t = tg * 4 + tt;
        const int idx = t * NCH + col;
        float sum = 0.0f;
        #pragma unroll
        for (int p = 0; p < SPLITK; p++) sum += g_partial[p][idx];
        pot_s[t][c] = sum;
        if (sum > THRESHV) cnt++;
    }
    cnt_s[tg][c] = cnt;
    __syncthreads();

    if (tid < 64) {
        int total = 0;
        #pragma unroll
        for (int gidx = 0; gidx < 16; gidx++) total += cnt_s[gidx][c];
        int fi = T_DIM - total;
        if (fi > T_DIM - 1) fi = T_DIM - 1;
        if (fi < 0) fi = 0;
        float o = pot_s[fi][c];
        g_cnt[col] = total;
        g_fp[col]  = (o > THRESHV) ? o : 0.0f;
    }

    // ---- Grid sync (ticket barrier, monotonic across graph replays) ----
    __threadfence();
    __syncthreads();
    if (tid == 0) {
        unsigned int ticket = atomicAdd(&g_tickets, 1u);
        tgt_s = (ticket / 32u + 1u) * 32u;
    }
    __syncthreads();
    if (tid == 0) {
        volatile unsigned int* vc = &g_tickets;
        while (*vc < tgt_s) { }
    }
    __syncthreads();
    __threadfence();

    // ---- Phase 2: winners (redundant per block) ----
    const int k0 = tid, k1 = tid + 1024;
    const int cn0 = g_cnt[k0], cn1 = g_cnt[k1];
    const float fp0 = g_fp[k0], fp1 = g_fp[k1];

    // v = max over k of (cnt>0 ? fp : 0), reduced via shfl + smem
    float m = fmaxf((cn0 > 0) ? fp0 : 0.0f, (cn1 > 0) ? fp1 : 0.0f);
    #pragma unroll
    for (int o = 16; o > 0; o >>= 1)
        m = fmaxf(m, __shfl_down_sync(0xFFFFFFFFu, m, o));
    if (lane == 0) wv[wid] = m;
    __syncthreads();
    if (wid == 0) {
        float mm = wv[lane];
        #pragma unroll
        for (int o = 16; o > 0; o >>= 1)
            mm = fmaxf(mm, __shfl_down_sync(0xFFFFFFFFu, mm, o));
        if (lane == 0) bc_v = mm * (float)T_DIM;
    }
    __syncthreads();
    const float v = bc_v;

    // tot[k] = sequential fold of cnt copies of (fp + v)
    {
        const float t0 = fp0 + v;
        float s0 = 0.0f;
        for (int i = 0; i < cn0; i++) s0 += t0;
        tot_s[k0] = s0;
        const float t1 = fp1 + v;
        float s1 = 0.0f;
        for (int i = 0; i < cn1; i++) s1 += t1;
        tot_s[k1] = s1;
        coef_s[k0] = 0.0f;
        coef_s[k1] = 0.0f;
    }
    __syncthreads();

    // Iterative top-16 argmax (tie -> lowest index) via shfl reductions
    for (int it = 0; it < KWTA; it++) {
        float bv = tot_s[k0];
        int   bi = k0;
        cmb(bv, bi, tot_s[k1], k1);
        #pragma unroll
        for (int o = 16; o > 0; o >>= 1) {
            float ov = __shfl_down_sync(0xFFFFFFFFu, bv, o);
            int   oi = __shfl_down_sync(0xFFFFFFFFu, bi, o);
            cmb(bv, bi, ov, oi);
        }
        if (lane == 0) { wv[wid] = bv; wi[wid] = bi; }
        __syncthreads();
        if (wid == 0) {
            float fv = wv[lane];
            int   fi = wi[lane];
            #pragma unroll
            for (int o = 16; o > 0; o >>= 1) {
                float ov = __shfl_down_sync(0xFFFFFFFFu, fv, o);
                int   oi = __shfl_down_sync(0xFFFFFFFFu, fi, o);
                cmb(fv, fi, ov, oi);
            }
            if (lane == 0) {
                if (fv > 0.0f) coef_s[fi] = 1.0f;
                tot_s[fi] = -3.4e38f;
            }
        }
        __syncthreads();
    }

    // ---- Phase 3: output from smem pot tile ----
    const float cf = coef_s[col];
    #pragma unroll
    for (int tt = 0; tt < 4; tt++) {
        const int t = tg * 4 + tt;
        out[t * NCH + col] = (pot_s[t][c] > THRESHV && cf > 0.0f) ? 1.0f : 0.0f;
    }
}

// ---------------------------------------------------------------------------
extern "C" void kernel_launch(void* const* d_in, const int* in_sizes, int n_in,
                              void* d_out, int out_size) {
    const float* rec = (const float*)d_in[0];   // (64, 1, 256, 256)
    const float* w   = (const float*)d_in[1];   // (2048, 1, 256, 256)
    float* out = (float*)d_out;                 // (64, 2048, 1, 1) float32

    cudaFuncSetAttribute(gemm_mma, cudaFuncAttributeMaxDynamicSharedMemorySize,
                         SMEM_TOTAL);
    dim3 grid(NCH / 128, SPLITK);               // (16, 18) = 288 CTAs, <=2/SM
    gemm_mma<<<grid, 256, SMEM_TOTAL>>>(rec, w);
    fused_post<<<32, 1024>>>(out);
}

// round 11
// speedup vs baseline: 1.5785x; 1.0092x over previous
#include <cuda_runtime.h>
#include <cuda_bf16.h>
#include <cstdint>

// Problem constants
#define T_DIM   64
#define NCH     2048
#define KDIM    65536
#define THRESHV 16384.0f
#define KWTA    16

// GEMM config: 16 n-blocks x SPLITK 18 = 288 CTAs (<= 2 per SM, balanced)
#define SPLITK  18
#define BK      16

// fp32 staging ring: 4 stages x (A 64x16 fp32 = 4KB, B 128x16 fp32 = 8KB)
#define FPSTG   12288
#define FP_B    4096
// bf16 ring: 3 stages x 18432 (AH 0, AL 3072, BH 6144, BL 12288; 48B row stride)
#define BFBASE  49152
#define BFSTG   18432
#define RSTRIDE 48
#define AH_OFF  0
#define AL_OFF  3072
#define BH_OFF  6144
#define BL_OFF  12288
#define SMEM_TOTAL (BFBASE + 3 * BFSTG)   // 104448

#define POSTBLK 64   // fused_post grid size (all resident on 148 SMs)

// Static scratch (no allocations allowed)
__device__ float g_partial[SPLITK][T_DIM * NCH];   // 9.4 MB
__device__ int   g_cnt[NCH];
__device__ float g_fp[NCH];
__device__ unsigned int g_tickets = 0;   // monotonic grid-sync counter

// ---------------------------------------------------------------------------
// Helpers
// ---------------------------------------------------------------------------
__device__ __forceinline__ uint32_t smem_u32(const void* p) {
    uint32_t a;
    asm("{ .reg .u64 t; cvta.to.shared.u64 t, %1; cvt.u32.u64 %0, t; }"
        : "=r"(a) : "l"(p));
    return a;
}
__device__ __forceinline__ void cp16(uint32_t dst, const void* src) {
    asm volatile("cp.async.cg.shared.global [%0], [%1], 16;"
                 :: "r"(dst), "l"(src) : "memory");
}
#define CP_COMMIT() asm volatile("cp.async.commit_group;" ::: "memory")
#define CP_WAIT(n)  asm volatile("cp.async.wait_group %0;" :: "n"(n) : "memory")

// Split float2 -> hi bf16x2 (RN) + lo bf16x2 (residual). Proven exact R3-R10.
__device__ __forceinline__ void split2(float x, float y, uint32_t& h, uint32_t& l) {
    asm("cvt.rn.bf16x2.f32 %0, %1, %2;" : "=r"(h) : "f"(y), "f"(x));
    float hx = __uint_as_float(h << 16);
    float hy = __uint_as_float(h & 0xFFFF0000u);
    float lx = x - hx;
    float ly = y - hy;
    asm("cvt.rn.bf16x2.f32 %0, %1, %2;" : "=r"(l) : "f"(ly), "f"(lx));
}

__device__ __forceinline__ void mma16816(float* c, const uint32_t* a,
                                         uint32_t b0, uint32_t b1) {
    asm volatile(
        "mma.sync.aligned.m16n8k16.row.col.f32.bf16.bf16.f32 "
        "{%0,%1,%2,%3}, {%4,%5,%6,%7}, {%8,%9}, {%0,%1,%2,%3};"
        : "+f"(c[0]), "+f"(c[1]), "+f"(c[2]), "+f"(c[3])
        : "r"(a[0]), "r"(a[1]), "r"(a[2]), "r"(a[3]), "r"(b0), "r"(b1));
}

__device__ __forceinline__ void ldsm4(uint32_t* r, uint32_t addr) {
    asm volatile("ldmatrix.sync.aligned.m8n8.x4.shared.b16 {%0,%1,%2,%3}, [%4];"
                 : "=r"(r[0]), "=r"(r[1]), "=r"(r[2]), "=r"(r[3]) : "r"(addr));
}

__device__ __forceinline__ void cvt_sts(const char* fp, char* hiP, char* loP) {
    float4 v = *(const float4*)fp;
    uint32_t h0, l0, h1, l1;
    split2(v.x, v.y, h0, l0);
    split2(v.z, v.w, h1, l1);
    *(uint2*)hiP = make_uint2(h0, h1);
    *(uint2*)loP = make_uint2(l0, l1);
}

// (val, idx) comparator: higher val wins, tie -> lower idx. Matches lax.top_k.
__device__ __forceinline__ void cmb(float& bv, int& bi, float ov, int oi) {
    if (ov > bv || (ov == bv && oi < bi)) { bv = ov; bi = oi; }
}

// ---------------------------------------------------------------------------
// Kernel 1: bf16 HMMA split-K GEMM (byte-identical structure to R8-R10).
// ---------------------------------------------------------------------------
__global__ void __launch_bounds__(256, 2)
gemm_mma(const float* __restrict__ rec, const float* __restrict__ w) {
    extern __shared__ char sm[];
    const uint32_t sbase = smem_u32(sm);

    const int tid  = threadIdx.x;
    const int wid  = tid >> 5;
    const int lane = tid & 31;
    const int g    = lane >> 2;
    const int q    = lane & 3;
    const int wm   = wid >> 2;
    const int wn   = wid & 3;
    const int nblk = blockIdx.x * 128;
    const int s    = blockIdx.y;
    const int nit  = (s < 10) ? 228 : 227;
    const int ch0  = (s < 10) ? s * 228 : 2280 + (s - 10) * 227;
    const size_t k0 = (size_t)ch0 * BK;

    const int lr  = tid >> 2;
    const int lkc = (tid & 3) * 4;
    const float* aS  = rec + (size_t)lr * KDIM + k0 + lkc;
    const float* bS0 = w + (size_t)(nblk + lr) * KDIM + k0 + lkc;
    const float* bS1 = bS0 + (size_t)64 * KDIM;
    const uint32_t fpA = (uint32_t)lr * 64 + lkc * 4;
    const uint32_t fpB = FP_B + (uint32_t)lr * 64 + lkc * 4;
    const uint32_t bfO = (uint32_t)lr * RSTRIDE + lkc * 2;

    const int j  = lane >> 3;
    const int l7 = lane & 7;
    const uint32_t aOff = (uint32_t)(wm * 32 + (j & 1) * 8 + l7) * RSTRIDE
                        + (j >> 1) * 16 + AH_OFF;
    const uint32_t bOff = (uint32_t)(wn * 32 + (j >> 1) * 8 + l7) * RSTRIDE
                        + (j & 1) * 16 + BH_OFF;

    float acc[2][4][4];
    #pragma unroll
    for (int m = 0; m < 2; m++)
        #pragma unroll
        for (int n = 0; n < 4; n++)
            #pragma unroll
            for (int i = 0; i < 4; i++) acc[m][n][i] = 0.0f;

    #pragma unroll
    for (int st = 0; st < 3; st++) {
        const uint32_t fo = sbase + st * FPSTG;
        const int co = st * BK;
        cp16(fo + fpA, aS + co);
        cp16(fo + fpB, bS0 + co);
        cp16(fo + fpB + 4096, bS1 + co);
        CP_COMMIT();
    }
    CP_WAIT(2);
    {
        const char* fs = sm;
        char* bs = sm + BFBASE;
        cvt_sts(fs + fpA, bs + AH_OFF + bfO, bs + AL_OFF + bfO);
        cvt_sts(fs + fpB, bs + BH_OFF + bfO, bs + BL_OFF + bfO);
        cvt_sts(fs + fpB + 4096, bs + BH_OFF + 3072 + bfO, bs + BL_OFF + 3072 + bfO);
    }

    int bfc = 0;

    #pragma unroll 1
    for (int it = 0; it < nit; it++) {
        const int nc = it + 3;
        if (nc < nit) {
            const uint32_t fo = sbase + (nc & 3) * FPSTG;
            const int co = nc * BK;
            cp16(fo + fpA, aS + co);
            cp16(fo + fpB, bS0 + co);
            cp16(fo + fpB + 4096, bS1 + co);
        }
        CP_COMMIT();
        CP_WAIT(2);
        __syncthreads();

        const int bfn = (bfc == 2) ? 0 : bfc + 1;
        if (it + 1 < nit) {
            const char* fs = sm + ((it + 1) & 3) * FPSTG;
            char* bs = sm + BFBASE + bfn * BFSTG;
            cvt_sts(fs + fpA, bs + AH_OFF + bfO, bs + AL_OFF + bfO);
            cvt_sts(fs + fpB, bs + BH_OFF + bfO, bs + BL_OFF + bfO);
            cvt_sts(fs + fpB + 4096, bs + BH_OFF + 3072 + bfO,
                    bs + BL_OFF + 3072 + bfO);
        }

        const uint32_t sb = sbase + BFBASE + bfc * BFSTG;
        uint32_t Ah0[4], Ah1[4], Al0[4], Al1[4];
        ldsm4(Ah0, sb + aOff);
        ldsm4(Ah1, sb + aOff + 16 * RSTRIDE);
        ldsm4(Al0, sb + aOff + (AL_OFF - AH_OFF));
        ldsm4(Al1, sb + aOff + (AL_OFF - AH_OFF) + 16 * RSTRIDE);
        uint32_t Bh0[4], Bh1[4], Bl0[4], Bl1[4];
        ldsm4(Bh0, sb + bOff);
        ldsm4(Bh1, sb + bOff + 16 * RSTRIDE);
        ldsm4(Bl0, sb + bOff + (BL_OFF - BH_OFF));
        ldsm4(Bl1, sb + bOff + (BL_OFF - BH_OFF) + 16 * RSTRIDE);

        const uint32_t* Bh[4] = { &Bh0[0], &Bh0[2], &Bh1[0], &Bh1[2] };
        const uint32_t* Bl[4] = { &Bl0[0], &Bl0[2], &Bl1[0], &Bl1[2] };
        const uint32_t* Ah[2] = { Ah0, Ah1 };
        const uint32_t* Al[2] = { Al0, Al1 };

        #pragma unroll
        for (int m = 0; m < 2; m++) {
            #pragma unroll
            for (int n = 0; n < 4; n++) {
                mma16816(acc[m][n], Ah[m], Bh[n][0], Bh[n][1]);
                mma16816(acc[m][n], Ah[m], Bl[n][0], Bl[n][1]);
                mma16816(acc[m][n], Al[m], Bh[n][0], Bh[n][1]);
            }
        }
        bfc = bfn;
    }

    float* gp = g_partial[s];
    const int t0 = wm * 32;
    #pragma unroll
    for (int m = 0; m < 2; m++) {
        const int r0 = t0 + m * 16 + g;
        #pragma unroll
        for (int n = 0; n < 4; n++) {
            const int cb = nblk + wn * 32 + n * 8 + 2 * q;
            *(float2*)&gp[r0 * NCH + cb]       = make_float2(acc[m][n][0], acc[m][n][1]);
            *(float2*)&gp[(r0 + 8) * NCH + cb] = make_float2(acc[m][n][2], acc[m][n][3]);
        }
    }
}

// ---------------------------------------------------------------------------
// Kernel 2: fused post-processing. 64 blocks x 1024 threads, one grid sync.
// Block b owns columns [b*32, b*32+32); warp spans 32 consecutive columns
// (full 128B line coalescing on g_partial reads).
// ---------------------------------------------------------------------------
__global__ void __launch_bounds__(1024)
fused_post(float* __restrict__ out) {
    __shared__ float pot_s[T_DIM][32];      // [t][c] 8 KB
    __shared__ int   cs[32][32];            // count tree, 4 KB
    __shared__ float tot_s[NCH];            // 8 KB
    __shared__ float coef_s[NCH];           // 8 KB
    __shared__ float wv[32];
    __shared__ int   wi[32];
    __shared__ float bc_v;
    __shared__ unsigned int tgt_s;

    const int tid  = threadIdx.x;
    const int lane = tid & 31;
    const int wid  = tid >> 5;
    const int c    = tid & 31;              // column within block
    const int tq   = tid >> 5;              // 0..31 -> t rows tq, tq+32
    const int col  = blockIdx.x * 32 + c;

    // ---- Phase 1: reduce partials -> pot tile (2 elements per thread) ----
    {
        const int i0 = tq * NCH + col;
        const int i1 = (tq + 32) * NCH + col;
        float s0 = 0.0f, s1 = 0.0f;
        #pragma unroll
        for (int p = 0; p < SPLITK; p++) {
            s0 += g_partial[p][i0];
            s1 += g_partial[p][i1];
        }
        pot_s[tq][c]      = s0;
        pot_s[tq + 32][c] = s1;
        cs[tq][c] = (s0 > THRESHV ? 1 : 0) + (s1 > THRESHV ? 1 : 0);
    }
    __syncthreads();

    // Count reduce over t (tree in smem)
    #pragma unroll
    for (int st = 16; st > 0; st >>= 1) {
        if (tid < st * 32) cs[tq][c] += cs[tq + st][c];
        __syncthreads();
    }

    if (tid < 32) {
        const int kcol = blockIdx.x * 32 + tid;
        int total = cs[0][tid];
        int fi = T_DIM - total;
        if (fi > T_DIM - 1) fi = T_DIM - 1;
        if (fi < 0) fi = 0;
        float o = pot_s[fi][tid];
        g_cnt[kcol] = total;
        g_fp[kcol]  = (o > THRESHV) ? o : 0.0f;
    }

    // ---- Grid sync (ticket barrier, monotonic across graph replays) ----
    __threadfence();
    __syncthreads();
    if (tid == 0) {
        unsigned int ticket = atomicAdd(&g_tickets, 1u);
        tgt_s = (ticket / (unsigned)POSTBLK + 1u) * (unsigned)POSTBLK;
    }
    __syncthreads();
    if (tid == 0) {
        volatile unsigned int* vc = &g_tickets;
        while (*vc < tgt_s) { }
    }
    __syncthreads();
    __threadfence();

    // ---- Phase 2: winners (redundant per block; shfl comparator R10) ----
    const int k0 = tid, k1 = tid + 1024;
    const int cn0 = g_cnt[k0], cn1 = g_cnt[k1];
    const float fp0 = g_fp[k0], fp1 = g_fp[k1];

    float m = fmaxf((cn0 > 0) ? fp0 : 0.0f, (cn1 > 0) ? fp1 : 0.0f);
    #pragma unroll
    for (int o = 16; o > 0; o >>= 1)
        m = fmaxf(m, __shfl_down_sync(0xFFFFFFFFu, m, o));
    if (lane == 0) wv[wid] = m;
    __syncthreads();
    if (wid == 0) {
        float mm = wv[lane];
        #pragma unroll
        for (int o = 16; o > 0; o >>= 1)
            mm = fmaxf(mm, __shfl_down_sync(0xFFFFFFFFu, mm, o));
        if (lane == 0) bc_v = mm * (float)T_DIM;
    }
    __syncthreads();
    const float v = bc_v;

    {
        const float t0 = fp0 + v;
        float s0 = 0.0f;
        for (int i = 0; i < cn0; i++) s0 += t0;
        tot_s[k0] = s0;
        const float t1 = fp1 + v;
        float s1 = 0.0f;
        for (int i = 0; i < cn1; i++) s1 += t1;
        tot_s[k1] = s1;
        coef_s[k0] = 0.0f;
        coef_s[k1] = 0.0f;
    }
    __syncthreads();

    for (int it = 0; it < KWTA; it++) {
        float bv = tot_s[k0];
        int   bi = k0;
        cmb(bv, bi, tot_s[k1], k1);
        #pragma unroll
        for (int o = 16; o > 0; o >>= 1) {
            float ov = __shfl_down_sync(0xFFFFFFFFu, bv, o);
            int   oi = __shfl_down_sync(0xFFFFFFFFu, bi, o);
            cmb(bv, bi, ov, oi);
        }
        if (lane == 0) { wv[wid] = bv; wi[wid] = bi; }
        __syncthreads();
        if (wid == 0) {
            float fv = wv[lane];
            int   fi = wi[lane];
            #pragma unroll
            for (int o = 16; o > 0; o >>= 1) {
                float ov = __shfl_down_sync(0xFFFFFFFFu, fv, o);
                int   oi = __shfl_down_sync(0xFFFFFFFFu, fi, o);
                cmb(fv, fi, ov, oi);
            }
            if (lane == 0) {
                if (fv > 0.0f) coef_s[fi] = 1.0f;
                tot_s[fi] = -3.4e38f;
            }
        }
        __syncthreads();
    }

    // ---- Phase 3: output from smem pot tile ----
    const float cf = coef_s[col];
    out[tq * NCH + col] =
        (pot_s[tq][c] > THRESHV && cf > 0.0f) ? 1.0f : 0.0f;
    out[(tq + 32) * NCH + col] =
        (pot_s[tq + 32][c] > THRESHV && cf > 0.0f) ? 1.0f : 0.0f;
}

// ---------------------------------------------------------------------------
extern "C" void kernel_launch(void* const* d_in, const int* in_sizes, int n_in,
                              void* d_out, int out_size) {
    const float* rec = (const float*)d_in[0];   // (64, 1, 256, 256)
    const float* w   = (const float*)d_in[1];   // (2048, 1, 256, 256)
    float* out = (float*)d_out;                 // (64, 2048, 1, 1) float32

    cudaFuncSetAttribute(gemm_mma, cudaFuncAttributeMaxDynamicSharedMemorySize,
                         SMEM_TOTAL);
    dim3 grid(NCH / 128, SPLITK);               // (16, 18) = 288 CTAs, <=2/SM
    gemm_mma<<<grid, 256, SMEM_TOTAL>>>(rec, w);
    fused_post<<<POSTBLK, 1024>>>(out);
}